// round 1
// baseline (speedup 1.0000x reference)
#include <cuda_runtime.h>
#include <math.h>

// Problem constants
#define B_ 8
#define S_ 2048
#define D_ 512
#define Q_ 8
#define C_ 1024
#define T_ (B_*S_)          // 16384 tokens

// Tiling
#define TM 64               // tokens per CTA
#define CN 128              // codes per chunk
#define KT 32               // k tile
#define NTHREADS 256
#define RES_STRIDE (D_+4)   // 516 floats: 16B aligned rows, stride % 32 banks == 4
#define CB_STRIDE  (KT+4)   // 36 floats

#define SMEM_FLOATS (TM*RES_STRIDE + CN*CB_STRIDE + TM*Q_)
#define SMEM_BYTES  (SMEM_FLOATS*4)

__device__ float g_cnorm[Q_*C_];
__device__ float g_loss[Q_];

// ---------------------------------------------------------------------------
// Kernel 0: per-code squared norms + zero loss accumulators (every replay)
// ---------------------------------------------------------------------------
__global__ void rvq_prep_kernel(const float* __restrict__ cbs) {
    int r = blockIdx.x*blockDim.x + threadIdx.x;
    if (r < Q_*C_) {
        const float4* p = (const float4*)(cbs + (size_t)r*D_);
        float s = 0.f;
        #pragma unroll 8
        for (int i = 0; i < D_/4; i++) {
            float4 v = p[i];
            s = fmaf(v.x, v.x, s); s = fmaf(v.y, v.y, s);
            s = fmaf(v.z, v.z, s); s = fmaf(v.w, v.w, s);
        }
        g_cnorm[r] = s;
    }
    if (r < Q_) g_loss[r] = 0.f;
}

// ---------------------------------------------------------------------------
// Main kernel: each CTA owns 64 tokens, loops over the 8 quantizer layers.
// ---------------------------------------------------------------------------
__global__ __launch_bounds__(NTHREADS, 1)
void rvq_main_kernel(const float* __restrict__ x,
                     const float* __restrict__ cbs,
                     float* __restrict__ out, int out_size) {
    extern __shared__ float smem[];
    float* s_res = smem;                          // [TM][RES_STRIDE]
    float* s_cb  = smem + TM*RES_STRIDE;          // [CN][CB_STRIDE]
    int*   s_idx = (int*)(s_cb + CN*CB_STRIDE);   // [TM][Q_]

    const int tid = threadIdx.x;
    const int w = tid >> 5;       // warp 0..7
    const int l = tid & 31;       // lane
    const size_t tok0 = (size_t)blockIdx.x * TM;

    // Load x tile into shared residual
    for (int i = tid; i < TM*(D_/4); i += NTHREADS) {
        int row = i >> 7;         // /128
        int c4  = i & 127;
        float4 v = ((const float4*)(x + (tok0+row)*D_))[c4];
        *(float4*)(s_res + row*RES_STRIDE + c4*4) = v;
    }
    __syncthreads();

    for (int q = 0; q < Q_; q++) {
        const float* cbq = cbs + (size_t)q*C_*D_;
        const float* cnq = g_cnorm + q*C_;

        float best_s[8];
        int   best_i[8];
        #pragma unroll
        for (int i = 0; i < 8; i++) { best_s[i] = 3.4e38f; best_i[i] = 0x7fffffff; }

        for (int chunk = 0; chunk < C_/CN; chunk++) {
            const int code0 = chunk*CN;
            float acc[8][4];
            #pragma unroll
            for (int i = 0; i < 8; i++)
                #pragma unroll
                for (int j = 0; j < 4; j++) acc[i][j] = 0.f;

            for (int kt = 0; kt < D_; kt += KT) {
                __syncthreads();   // protect previous tile readers
                // cooperative load of 128x32 codebook tile
                for (int i = tid; i < CN*(KT/4); i += NTHREADS) {
                    int row = i >> 3;
                    int c4  = i & 7;
                    float4 v = *(const float4*)(cbq + (size_t)(code0+row)*D_ + kt + c4*4);
                    *(float4*)(s_cb + row*CB_STRIDE + c4*4) = v;
                }
                __syncthreads();

                #pragma unroll
                for (int k4 = 0; k4 < KT; k4 += 4) {
                    float4 a[8];
                    #pragma unroll
                    for (int i = 0; i < 8; i++)
                        a[i] = *(float4*)(s_res + (w*8+i)*RES_STRIDE + kt + k4);
                    float4 b[4];
                    #pragma unroll
                    for (int j = 0; j < 4; j++)
                        b[j] = *(float4*)(s_cb + (l + 32*j)*CB_STRIDE + k4);
                    #pragma unroll
                    for (int i = 0; i < 8; i++) {
                        #pragma unroll
                        for (int j = 0; j < 4; j++) {
                            float s = acc[i][j];
                            s = fmaf(a[i].x, b[j].x, s);
                            s = fmaf(a[i].y, b[j].y, s);
                            s = fmaf(a[i].z, b[j].z, s);
                            s = fmaf(a[i].w, b[j].w, s);
                            acc[i][j] = s;
                        }
                    }
                }
            }

            // score = cnorm - 2*dot ; warp-level argmin (first-occurrence ties)
            float cn[4];
            #pragma unroll
            for (int j = 0; j < 4; j++) cn[j] = cnq[code0 + l + 32*j];

            #pragma unroll
            for (int i = 0; i < 8; i++) {
                float bs = 3.4e38f; int bi = 0x7fffffff;
                #pragma unroll
                for (int j = 0; j < 4; j++) {
                    float sc = fmaf(-2.f, acc[i][j], cn[j]);
                    int ci = code0 + l + 32*j;
                    if (sc < bs || (sc == bs && ci < bi)) { bs = sc; bi = ci; }
                }
                #pragma unroll
                for (int off = 16; off > 0; off >>= 1) {
                    float os = __shfl_down_sync(0xffffffffu, bs, off);
                    int   oi = __shfl_down_sync(0xffffffffu, bi, off);
                    if (os < bs || (os == bs && oi < bi)) { bs = os; bi = oi; }
                }
                bs = __shfl_sync(0xffffffffu, bs, 0);
                bi = __shfl_sync(0xffffffffu, bi, 0);
                if (bs < best_s[i] || (bs == best_s[i] && bi < best_i[i])) {
                    best_s[i] = bs; best_i[i] = bi;
                }
            }
        }

        // Residual update for this warp's 8 tokens (disjoint rows -> no CTA sync
        // needed here; the __syncthreads at the next tile load fences s_cb reuse).
        // commit loss == mean(new_residual^2).
        float lloss = 0.f;
        #pragma unroll
        for (int i = 0; i < 8; i++) {
            const int tokr = w*8 + i;
            const int bi = best_i[i];
            if (l == 0) s_idx[tokr*Q_ + q] = bi;
            const float* qc = cbq + (size_t)bi*D_;
            #pragma unroll
            for (int it = 0; it < 4; it++) {
                int d4 = l*4 + it*128;
                float4 cv = *(const float4*)(qc + d4);
                float4 rv = *(float4*)(s_res + tokr*RES_STRIDE + d4);
                rv.x -= cv.x; rv.y -= cv.y; rv.z -= cv.z; rv.w -= cv.w;
                *(float4*)(s_res + tokr*RES_STRIDE + d4) = rv;
                lloss = fmaf(rv.x, rv.x, lloss);
                lloss = fmaf(rv.y, rv.y, lloss);
                lloss = fmaf(rv.z, rv.z, lloss);
                lloss = fmaf(rv.w, rv.w, lloss);
            }
        }
        #pragma unroll
        for (int off = 16; off > 0; off >>= 1)
            lloss += __shfl_down_sync(0xffffffffu, lloss, off);
        if (l == 0) atomicAdd(&g_loss[q], lloss);
    }
    __syncthreads();

    // quantized_out = x - residual_final
    for (int i = tid; i < TM*(D_/4); i += NTHREADS) {
        int row = i >> 7;
        int c4  = i & 127;
        float4 xv = ((const float4*)(x + (tok0+row)*D_))[c4];
        float4 rv = *(float4*)(s_res + row*RES_STRIDE + c4*4);
        float4 ov = make_float4(xv.x-rv.x, xv.y-rv.y, xv.z-rv.z, xv.w-rv.w);
        ((float4*)(out + (tok0+row)*D_))[c4] = ov;
    }
    // indices [b,n,q] as float (exactly representable <= 1023)
    if (out_size >= (long long)T_*D_ + (long long)T_*Q_) {
        for (int i = tid; i < TM*Q_; i += NTHREADS) {
            out[(size_t)T_*D_ + tok0*Q_ + i] = (float)s_idx[i];
        }
    }
}

// ---------------------------------------------------------------------------
// Finalize: losses[q] = sum(residual_q^2) / (B*S*D)
// ---------------------------------------------------------------------------
__global__ void rvq_fin_kernel(float* __restrict__ out, int out_size) {
    int q = threadIdx.x;
    if (q < Q_ && out_size >= (long long)T_*D_ + (long long)T_*Q_ + Q_) {
        out[(size_t)T_*D_ + (size_t)T_*Q_ + q] = g_loss[q] / (float)((long long)T_*D_);
    }
}

// ---------------------------------------------------------------------------
extern "C" void kernel_launch(void* const* d_in, const int* in_sizes, int n_in,
                              void* d_out, int out_size) {
    // identify inputs by size for safety (x: 8.39M, codebooks: 4.19M)
    const float* x;
    const float* cbs;
    if (in_sizes[0] == T_*D_) { x = (const float*)d_in[0]; cbs = (const float*)d_in[1]; }
    else                      { x = (const float*)d_in[1]; cbs = (const float*)d_in[0]; }
    float* out = (float*)d_out;

    cudaFuncSetAttribute(rvq_main_kernel,
                         cudaFuncAttributeMaxDynamicSharedMemorySize, SMEM_BYTES);

    rvq_prep_kernel<<<(Q_*C_ + 255)/256, 256>>>(cbs);
    rvq_main_kernel<<<T_/TM, NTHREADS, SMEM_BYTES>>>(x, cbs, out, out_size);
    rvq_fin_kernel<<<1, 32>>>(out, out_size);
}

// round 2
// speedup vs baseline: 1.2158x; 1.2158x over previous
#include <cuda_runtime.h>

// Problem constants
#define B_ 8
#define S_ 2048
#define D_ 512
#define Q_ 8
#define C_ 1024
#define T_ (B_*S_)          // 16384 tokens

// Tiling
#define TM 64               // tokens per CTA
#define CN 128              // codes per chunk
#define KT 32               // k tile
#define NTHREADS 256
#define RES_STRIDE (D_+4)   // 516 floats
#define CB_STRIDE  (KT+4)   // 36 floats
#define NTILES (Q_*(C_/CN)*(D_/KT))   // 1024 k-tiles total

// smem: residual + 2 codebook buffers + cnorm copy + indices
#define SMEM_FLOATS (TM*RES_STRIDE + 2*CN*CB_STRIDE + Q_*C_ + TM*Q_)
#define SMEM_BYTES  (SMEM_FLOATS*4)

typedef unsigned long long u64;

__device__ float g_cnorm[Q_*C_];
__device__ float g_loss[Q_];

__device__ __forceinline__ u64 ffma2(u64 a, u64 b, u64 c) {
    u64 d;
    asm("fma.rn.f32x2 %0, %1, %2, %3;" : "=l"(d) : "l"(a), "l"(b), "l"(c));
    return d;
}
__device__ __forceinline__ void cp_async16(float* smem_dst, const float* gsrc) {
    unsigned s = (unsigned)__cvta_generic_to_shared(smem_dst);
    asm volatile("cp.async.cg.shared.global [%0], [%1], 16;" :: "r"(s), "l"(gsrc));
}
#define CP_COMMIT() asm volatile("cp.async.commit_group;" ::: "memory")
#define CP_WAIT1()  asm volatile("cp.async.wait_group 1;" ::: "memory")

// ---------------------------------------------------------------------------
// Kernel 0: per-code squared norms + zero loss accumulators (every replay)
// ---------------------------------------------------------------------------
__global__ void rvq_prep_kernel(const float* __restrict__ cbs) {
    int r = blockIdx.x*blockDim.x + threadIdx.x;
    if (r < Q_*C_) {
        const float4* p = (const float4*)(cbs + (size_t)r*D_);
        float s = 0.f;
        #pragma unroll 8
        for (int i = 0; i < D_/4; i++) {
            float4 v = p[i];
            s = fmaf(v.x, v.x, s); s = fmaf(v.y, v.y, s);
            s = fmaf(v.z, v.z, s); s = fmaf(v.w, v.w, s);
        }
        g_cnorm[r] = s;
    }
    if (r < Q_) g_loss[r] = 0.f;
}

// issue cp.async for k-tile t into buf
__device__ __forceinline__ void load_tile(const float* __restrict__ cbs,
                                          int t, float* buf, int tid) {
    int q    = t >> 7;               // /128 tiles per q
    int rem  = t & 127;
    int code0 = (rem >> 4) * CN;     // 16 k-tiles per chunk
    int kt0   = (rem & 15) * KT;
    const float* base = cbs + (size_t)q*C_*D_;
    #pragma unroll
    for (int it = 0; it < 4; it++) {
        int i   = tid + it*NTHREADS; // 0..1023 16B chunks
        int row = i >> 3;
        int c4  = i & 7;
        cp_async16(buf + row*CB_STRIDE + c4*4,
                   base + (size_t)(code0+row)*D_ + kt0 + c4*4);
    }
}

// ---------------------------------------------------------------------------
// Main kernel
// ---------------------------------------------------------------------------
__global__ __launch_bounds__(NTHREADS, 1)
void rvq_main_kernel(const float* __restrict__ x,
                     const float* __restrict__ cbs,
                     float* __restrict__ out, int out_size) {
    extern __shared__ float smem[];
    float* s_res = smem;                              // [TM][RES_STRIDE]
    float* s_cb0 = s_res + TM*RES_STRIDE;             // 2 x [CN][CB_STRIDE]
    float* s_cn  = s_cb0 + 2*CN*CB_STRIDE;            // [Q_*C_]
    int*   s_idx = (int*)(s_cn + Q_*C_);              // [TM][Q_]

    const int tid = threadIdx.x;
    const int w = tid >> 5;
    const int l = tid & 31;
    const size_t tok0 = (size_t)blockIdx.x * TM;
    float* bufs[2] = { s_cb0, s_cb0 + CN*CB_STRIDE };

    // start pipeline immediately: tile 0 in flight while we fill s_res / s_cn
    load_tile(cbs, 0, bufs[0], tid);
    CP_COMMIT();

    for (int i = tid; i < TM*(D_/4); i += NTHREADS) {
        int row = i >> 7;
        int c4  = i & 127;
        float4 v = ((const float4*)(x + (tok0+row)*D_))[c4];
        *(float4*)(s_res + row*RES_STRIDE + c4*4) = v;
    }
    for (int i = tid; i < Q_*C_; i += NTHREADS) s_cn[i] = g_cnorm[i];

    int t = 0;
    for (int q = 0; q < Q_; q++) {
        const float* cbq = cbs + (size_t)q*C_*D_;

        float best_s[8];
        int   best_i[8];
        #pragma unroll
        for (int i = 0; i < 8; i++) { best_s[i] = 3.4e38f; best_i[i] = 0x7fffffff; }

        for (int chunk = 0; chunk < C_/CN; chunk++) {
            const int code0 = chunk*CN;
            u64 acc[8][4];
            #pragma unroll
            for (int i = 0; i < 8; i++)
                #pragma unroll
                for (int j = 0; j < 4; j++) acc[i][j] = 0ull;

            for (int kti = 0; kti < D_/KT; kti++) {
                __syncthreads();             // prev readers of next buffer done
                if (t+1 < NTILES) load_tile(cbs, t+1, bufs[(t+1)&1], tid);
                CP_COMMIT();
                CP_WAIT1();                  // tile t resident
                __syncthreads();

                const float* cb   = bufs[t&1];
                const float* ares = s_res + (w*8)*RES_STRIDE + kti*KT;
                #pragma unroll
                for (int k4 = 0; k4 < KT; k4 += 4) {
                    ulonglong2 a[8];
                    #pragma unroll
                    for (int i = 0; i < 8; i++)
                        a[i] = *(const ulonglong2*)(ares + i*RES_STRIDE + k4);
                    ulonglong2 b[4];
                    #pragma unroll
                    for (int j = 0; j < 4; j++)
                        b[j] = *(const ulonglong2*)(cb + (l+32*j)*CB_STRIDE + k4);
                    #pragma unroll
                    for (int i = 0; i < 8; i++) {
                        #pragma unroll
                        for (int j = 0; j < 4; j++) {
                            acc[i][j] = ffma2(a[i].x, b[j].x, acc[i][j]);
                            acc[i][j] = ffma2(a[i].y, b[j].y, acc[i][j]);
                        }
                    }
                }
                t++;
            }

            // score = cnorm - 2*dot ; warp argmin, first-occurrence ties
            float cn[4];
            #pragma unroll
            for (int j = 0; j < 4; j++) cn[j] = s_cn[q*C_ + code0 + l + 32*j];

            #pragma unroll
            for (int i = 0; i < 8; i++) {
                float bs = 3.4e38f; int bi = 0x7fffffff;
                #pragma unroll
                for (int j = 0; j < 4; j++) {
                    union { u64 u; float2 f; } cv; cv.u = acc[i][j];
                    float sc = fmaf(-2.f, cv.f.x + cv.f.y, cn[j]);
                    int ci = code0 + l + 32*j;
                    if (sc < bs || (sc == bs && ci < bi)) { bs = sc; bi = ci; }
                }
                #pragma unroll
                for (int off = 16; off > 0; off >>= 1) {
                    float os = __shfl_down_sync(0xffffffffu, bs, off);
                    int   oi = __shfl_down_sync(0xffffffffu, bi, off);
                    if (os < bs || (os == bs && oi < bi)) { bs = os; bi = oi; }
                }
                bs = __shfl_sync(0xffffffffu, bs, 0);
                bi = __shfl_sync(0xffffffffu, bi, 0);
                if (bs < best_s[i] || (bs == best_s[i] && bi < best_i[i])) {
                    best_s[i] = bs; best_i[i] = bi;
                }
            }
        }

        // residual update: warp-private rows, no CTA sync needed
        float lloss = 0.f;
        #pragma unroll
        for (int i = 0; i < 8; i++) {
            const int tokr = w*8 + i;
            const int bi = best_i[i];
            if (l == 0) s_idx[tokr*Q_ + q] = bi;
            const float* qc = cbq + (size_t)bi*D_;
            #pragma unroll
            for (int it = 0; it < 4; it++) {
                int d4 = l*4 + it*128;
                float4 cv = *(const float4*)(qc + d4);
                float4 rv = *(float4*)(s_res + tokr*RES_STRIDE + d4);
                rv.x -= cv.x; rv.y -= cv.y; rv.z -= cv.z; rv.w -= cv.w;
                *(float4*)(s_res + tokr*RES_STRIDE + d4) = rv;
                lloss = fmaf(rv.x, rv.x, lloss);
                lloss = fmaf(rv.y, rv.y, lloss);
                lloss = fmaf(rv.z, rv.z, lloss);
                lloss = fmaf(rv.w, rv.w, lloss);
            }
        }
        #pragma unroll
        for (int off = 16; off > 0; off >>= 1)
            lloss += __shfl_down_sync(0xffffffffu, lloss, off);
        if (l == 0) atomicAdd(&g_loss[q], lloss);
    }
    __syncthreads();

    // quantized_out = x - residual_final
    for (int i = tid; i < TM*(D_/4); i += NTHREADS) {
        int row = i >> 7;
        int c4  = i & 127;
        float4 xv = ((const float4*)(x + (tok0+row)*D_))[c4];
        float4 rv = *(float4*)(s_res + row*RES_STRIDE + c4*4);
        ((float4*)(out + (tok0+row)*D_))[c4] =
            make_float4(xv.x-rv.x, xv.y-rv.y, xv.z-rv.z, xv.w-rv.w);
    }
    // indices [b,n,q] as float
    if (out_size >= (long long)T_*D_ + (long long)T_*Q_) {
        for (int i = tid; i < TM*Q_; i += NTHREADS)
            out[(size_t)T_*D_ + tok0*Q_ + i] = (float)s_idx[i];
    }
}

// ---------------------------------------------------------------------------
__global__ void rvq_fin_kernel(float* __restrict__ out, int out_size) {
    int q = threadIdx.x;
    if (q < Q_ && out_size >= (long long)T_*D_ + (long long)T_*Q_ + Q_) {
        out[(size_t)T_*D_ + (size_t)T_*Q_ + q] = g_loss[q] / (float)((long long)T_*D_);
    }
}

// ---------------------------------------------------------------------------
extern "C" void kernel_launch(void* const* d_in, const int* in_sizes, int n_in,
                              void* d_out, int out_size) {
    const float* x;
    const float* cbs;
    if (in_sizes[0] == T_*D_) { x = (const float*)d_in[0]; cbs = (const float*)d_in[1]; }
    else                      { x = (const float*)d_in[1]; cbs = (const float*)d_in[0]; }
    float* out = (float*)d_out;

    cudaFuncSetAttribute(rvq_main_kernel,
                         cudaFuncAttributeMaxDynamicSharedMemorySize, SMEM_BYTES);

    rvq_prep_kernel<<<(Q_*C_ + 255)/256, 256>>>(cbs);
    rvq_main_kernel<<<T_/TM, NTHREADS, SMEM_BYTES>>>(x, cbs, out, out_size);
    rvq_fin_kernel<<<1, 32>>>(out, out_size);
}